// round 1
// baseline (speedup 1.0000x reference)
#include <cuda_runtime.h>
#include <cstdint>

#define H    1024
#define FH   4096
#define V    32000
#define SEQ  2048
#define GRID 148
#define NT   1024
#define NW   32            // warps per block
#define TW   (GRID * NW)   // total warps

// Cross-block scratch (allowed: __device__ globals, no allocation)
__device__ float g_g0[FH];
__device__ float g_g1[FH];
__device__ float g_pVal[GRID];
__device__ int   g_pIdx[GRID];
__device__ unsigned long long g_cnt;   // cumulative arrivals (monotonic across replays)
__device__ unsigned           g_rel;   // last released phase (monotonic across replays)

// Monotonic grid barrier: no reset, safe across graph replays.
__device__ __forceinline__ void gsync(unsigned target) {
    __syncthreads();
    if (threadIdx.x == 0) {
        __threadfence();
        unsigned long long arrived = atomicAdd(&g_cnt, 1ull) + 1ull;
        if (arrived == (unsigned long long)target * (unsigned long long)GRID) {
            atomicExch(&g_rel, target);
        } else {
            while (*(volatile unsigned*)&g_rel < target) { }
            __threadfence();
        }
    }
    __syncthreads();
}

__global__ void __launch_bounds__(NT, 1)
decoder_kernel(const int*   __restrict__ y,
               const float* __restrict__ ctx,
               const float* __restrict__ wih0,
               const float* __restrict__ whh0,
               const float* __restrict__ bih0,
               const float* __restrict__ bhh0,
               const float* __restrict__ wih1,
               const float* __restrict__ whh1,
               const float* __restrict__ bih1,
               const float* __restrict__ bhh1,
               const float* __restrict__ wfc,
               const float* __restrict__ bfc,
               float* __restrict__ out)
{
    __shared__ __align__(16) float hs0[H];
    __shared__ __align__(16) float hs1[H];
    __shared__ float cs0[H];
    __shared__ float cs1[H];
    __shared__ float sVal[NW];
    __shared__ int   sIdx[NW];
    __shared__ float sTok;
    __shared__ unsigned sBase;

    const int tid  = threadIdx.x;
    const int lane = tid & 31;
    const int warp = tid >> 5;
    const int gw   = blockIdx.x * NW + warp;

    if (tid == 0) sBase = *(volatile unsigned*)&g_rel;
    // h = c = context_vector (layer 0 row 0, layer 1 row 1), redundant per block
    hs0[tid] = cs0[tid] = ctx[tid];
    hs1[tid] = cs1[tid] = ctx[H + tid];
    __syncthreads();
    const unsigned base = sBase;
    unsigned phase = 0;

    // out row 0 = zeros
    for (int i = blockIdx.x * NT + tid; i < V; i += GRID * NT)
        out[i] = 0.0f;

    const float y0f = (float)__ldg(&y[0]);
    const float4* h0v = (const float4*)hs0;
    const float4* h1v = (const float4*)hs1;

    for (int t = 0; t < SEQ - 1; ++t) {
        // ---------- token for this step (redundant per block) ----------
        float x;
        if (t == 0) {
            x = y0f;
        } else {
            if (warp == 0) {
                float bv = -1.0f; int bi = 0x7fffffff;
                for (int i = lane; i < GRID; i += 32) {
                    float v  = __ldcg(&g_pVal[i]);
                    int   ix = __ldcg(&g_pIdx[i]);
                    if (v > bv || (v == bv && ix < bi)) { bv = v; bi = ix; }
                }
                #pragma unroll
                for (int off = 16; off; off >>= 1) {
                    float ov = __shfl_down_sync(0xffffffffu, bv, off);
                    int   oi = __shfl_down_sync(0xffffffffu, bi, off);
                    if (ov > bv || (ov == bv && oi < bi)) { bv = ov; bi = oi; }
                }
                if (lane == 0) sTok = (float)bi;
            }
            __syncthreads();
            x = sTok;
        }

        // ---------- phase 1: g0 = whh0 @ h0 + wih0*x + b_ih0 + b_hh0 ----------
        for (int row = gw; row < FH; row += TW) {
            const float4* w = (const float4*)(whh0 + (size_t)row * H);
            float acc = 0.f;
            #pragma unroll
            for (int k = 0; k < 8; ++k) {
                float4 a = w[lane + 32 * k];
                float4 b = h0v[lane + 32 * k];
                acc = fmaf(a.x, b.x, acc); acc = fmaf(a.y, b.y, acc);
                acc = fmaf(a.z, b.z, acc); acc = fmaf(a.w, b.w, acc);
            }
            #pragma unroll
            for (int off = 16; off; off >>= 1)
                acc += __shfl_down_sync(0xffffffffu, acc, off);
            if (lane == 0) {
                acc += wih0[row] * x + bih0[row] + bhh0[row];
                __stcg(&g_g0[row], acc);
            }
        }
        gsync(base + (++phase));

        // ---------- phase 2: cell 0 (redundant) + g1 matvec ----------
        {
            float gi = __ldcg(&g_g0[tid]);
            float gf = __ldcg(&g_g0[tid + H]);
            float gg = __ldcg(&g_g0[tid + 2 * H]);
            float go = __ldcg(&g_g0[tid + 3 * H]);
            float ii = 1.f / (1.f + expf(-gi));
            float ff = 1.f / (1.f + expf(-gf));
            float gt = tanhf(gg);
            float oo = 1.f / (1.f + expf(-go));
            float c  = ff * cs0[tid] + ii * gt;
            cs0[tid] = c;
            hs0[tid] = oo * tanhf(c);
        }
        __syncthreads();

        for (int row = gw; row < FH; row += TW) {
            const float4* wa = (const float4*)(wih1 + (size_t)row * H);
            const float4* wb = (const float4*)(whh1 + (size_t)row * H);
            float acc = 0.f;
            #pragma unroll
            for (int k = 0; k < 8; ++k) {
                float4 a  = wa[lane + 32 * k];
                float4 b  = h0v[lane + 32 * k];
                acc = fmaf(a.x, b.x, acc); acc = fmaf(a.y, b.y, acc);
                acc = fmaf(a.z, b.z, acc); acc = fmaf(a.w, b.w, acc);
                float4 a2 = wb[lane + 32 * k];
                float4 b2 = h1v[lane + 32 * k];
                acc = fmaf(a2.x, b2.x, acc); acc = fmaf(a2.y, b2.y, acc);
                acc = fmaf(a2.z, b2.z, acc); acc = fmaf(a2.w, b2.w, acc);
            }
            #pragma unroll
            for (int off = 16; off; off >>= 1)
                acc += __shfl_down_sync(0xffffffffu, acc, off);
            if (lane == 0) {
                acc += bih1[row] + bhh1[row];
                __stcg(&g_g1[row], acc);
            }
        }
        gsync(base + (++phase));

        // ---------- phase 3: cell 1 (redundant) + fc matvec + argmax ----------
        {
            float gi = __ldcg(&g_g1[tid]);
            float gf = __ldcg(&g_g1[tid + H]);
            float gg = __ldcg(&g_g1[tid + 2 * H]);
            float go = __ldcg(&g_g1[tid + 3 * H]);
            float ii = 1.f / (1.f + expf(-gi));
            float ff = 1.f / (1.f + expf(-gf));
            float gt = tanhf(gg);
            float oo = 1.f / (1.f + expf(-go));
            float c  = ff * cs1[tid] + ii * gt;
            cs1[tid] = c;
            hs1[tid] = oo * tanhf(c);
        }
        __syncthreads();

        float bv = -1.0f; int bi = 0x7fffffff;   // relu'd preds are >= 0
        float* orow = out + (size_t)(t + 1) * V;
        for (int row = gw; row < V; row += TW) {
            const float4* w = (const float4*)(wfc + (size_t)row * H);
            float acc = 0.f;
            #pragma unroll
            for (int k = 0; k < 8; ++k) {
                float4 a = __ldcs(&w[lane + 32 * k]);   // evict-first: keep LSTM weights in L2
                float4 b = h1v[lane + 32 * k];
                acc = fmaf(a.x, b.x, acc); acc = fmaf(a.y, b.y, acc);
                acc = fmaf(a.z, b.z, acc); acc = fmaf(a.w, b.w, acc);
            }
            #pragma unroll
            for (int off = 16; off; off >>= 1)
                acc += __shfl_down_sync(0xffffffffu, acc, off);
            if (lane == 0) {
                acc += bfc[row];
                float p = fmaxf(acc, 0.0f);
                __stcs(&orow[row], p);
                if (p > bv || (p == bv && row < bi)) { bv = p; bi = row; }
            }
        }
        if (lane == 0) { sVal[warp] = bv; sIdx[warp] = bi; }
        __syncthreads();
        if (warp == 0) {
            float v  = sVal[lane];
            int   ix = sIdx[lane];
            #pragma unroll
            for (int off = 16; off; off >>= 1) {
                float ov = __shfl_down_sync(0xffffffffu, v, off);
                int   oi = __shfl_down_sync(0xffffffffu, ix, off);
                if (ov > v || (ov == v && oi < ix)) { v = ov; ix = oi; }
            }
            if (lane == 0) {
                __stcg(&g_pVal[blockIdx.x], v);
                __stcg(&g_pIdx[blockIdx.x], ix);
            }
        }
        gsync(base + (++phase));
    }
}

extern "C" void kernel_launch(void* const* d_in, const int* in_sizes, int n_in,
                              void* d_out, int out_size) {
    const int*   y    = (const int*)  d_in[0];
    const float* ctx  = (const float*)d_in[1];
    const float* wih0 = (const float*)d_in[2];
    const float* whh0 = (const float*)d_in[3];
    const float* bih0 = (const float*)d_in[4];
    const float* bhh0 = (const float*)d_in[5];
    const float* wih1 = (const float*)d_in[6];
    const float* whh1 = (const float*)d_in[7];
    const float* bih1 = (const float*)d_in[8];
    const float* bhh1 = (const float*)d_in[9];
    const float* wfc  = (const float*)d_in[10];
    const float* bfc  = (const float*)d_in[11];
    float* out = (float*)d_out;

    decoder_kernel<<<GRID, NT>>>(y, ctx, wih0, whh0, bih0, bhh0,
                                 wih1, whh1, bih1, bhh1, wfc, bfc, out);
}

// round 2
// speedup vs baseline: 1.0736x; 1.0736x over previous
#include <cuda_runtime.h>
#include <cstdint>

#define H     1024
#define FH    4096
#define V     32000
#define SEQ   2048
#define GRID  148
#define NT    1024
#define NW    32            // warps per block
#define TW    (GRID * NW)   // total warps
#define NROWS (V + 2 * FH)  // fc rows + whh0 rows + whh1 rows fused in phase A

// Cross-block scratch (allowed: __device__ globals)
__device__ float g_hh0[FH];        // whh0 @ h0_t      (for step t+1's cell0)
__device__ float g_hh1[2][FH];     // whh1 @ h1_t, double-buffered (WAR across blocks)
__device__ float g_ih1[FH];        // wih1 @ h0_t + b_ih1 + b_hh1
__device__ float g_pVal[GRID];
__device__ int   g_pIdx[GRID];
__device__ unsigned long long g_cnt;  // cumulative arrivals (monotonic across graph replays)
__device__ unsigned           g_rel;  // last released phase (monotonic across graph replays)

// Monotonic grid barrier: no reset, safe across graph replays.
__device__ __forceinline__ void gsync(unsigned target) {
    __syncthreads();
    if (threadIdx.x == 0) {
        __threadfence();
        unsigned long long arrived = atomicAdd(&g_cnt, 1ull) + 1ull;
        if (arrived == (unsigned long long)target * (unsigned long long)GRID) {
            atomicExch(&g_rel, target);
        } else {
            while (*(volatile unsigned*)&g_rel < target) { }
            __threadfence();
        }
    }
    __syncthreads();
}

// 1024-long dot of a global row with an smem vector; full-warp collective,
// result valid on lane 0.  STREAM=1 uses evict-first loads (fc weights).
template <int STREAM>
__device__ __forceinline__ float dot1024(const float* __restrict__ w,
                                         const float4* __restrict__ hv,
                                         int lane) {
    const float4* wv = (const float4*)w;
    float acc = 0.f;
    #pragma unroll
    for (int k = 0; k < 8; ++k) {
        float4 a = STREAM ? __ldcs(&wv[lane + 32 * k]) : wv[lane + 32 * k];
        float4 b = hv[lane + 32 * k];
        acc = fmaf(a.x, b.x, acc); acc = fmaf(a.y, b.y, acc);
        acc = fmaf(a.z, b.z, acc); acc = fmaf(a.w, b.w, acc);
    }
    #pragma unroll
    for (int off = 16; off; off >>= 1)
        acc += __shfl_down_sync(0xffffffffu, acc, off);
    return acc;
}

__device__ __forceinline__ float sigm(float v) { return 1.f / (1.f + expf(-v)); }

__global__ void __launch_bounds__(NT, 1)
decoder_kernel(const int*   __restrict__ y,
               const float* __restrict__ ctx,
               const float* __restrict__ wih0,
               const float* __restrict__ whh0,
               const float* __restrict__ bih0,
               const float* __restrict__ bhh0,
               const float* __restrict__ wih1,
               const float* __restrict__ whh1,
               const float* __restrict__ bih1,
               const float* __restrict__ bhh1,
               const float* __restrict__ wfc,
               const float* __restrict__ bfc,
               float* __restrict__ out)
{
    __shared__ __align__(16) float hs0[H];
    __shared__ __align__(16) float hs1[H];
    __shared__ float cs0[H];
    __shared__ float cs1[H];
    __shared__ float sVal[NW];
    __shared__ int   sIdx[NW];
    __shared__ float sTok;
    __shared__ unsigned sBase;

    const int tid  = threadIdx.x;
    const int lane = tid & 31;
    const int warp = tid >> 5;
    const int gw   = blockIdx.x * NW + warp;

    if (tid == 0) sBase = *(volatile unsigned*)&g_rel;
    // h = c = context_vector, redundant per block
    hs0[tid] = cs0[tid] = ctx[tid];
    hs1[tid] = cs1[tid] = ctx[H + tid];
    __syncthreads();
    const unsigned base = sBase;
    unsigned phase = 0;

    const float4* h0v = (const float4*)hs0;
    const float4* h1v = (const float4*)hs1;

    // out row 0 = zeros
    for (int i = blockIdx.x * NT + tid; i < V; i += GRID * NT)
        out[i] = 0.0f;

    // ---- Prologue: whh0 @ ctx0 -> g_hh0 ; whh1 @ ctx1 -> g_hh1[1] ----
    for (int idx = gw; idx < 2 * FH; idx += TW) {
        float acc;
        if (idx < FH) {
            acc = dot1024<0>(whh0 + (size_t)idx * H, h0v, lane);
            if (lane == 0) __stcg(&g_hh0[idx], acc);
        } else {
            int r = idx - FH;
            acc = dot1024<0>(whh1 + (size_t)r * H, h1v, lane);
            if (lane == 0) __stcg(&g_hh1[1][r], acc);
        }
    }
    gsync(base + (++phase));

    const float y0f = (float)__ldg(&y[0]);

    for (int t = 0; t < SEQ - 1; ++t) {
        // ================= Phase B =================
        // token for this step (redundant per block)
        float x;
        if (t == 0) {
            x = y0f;
        } else {
            if (warp == 0) {
                float bv = -1.0f; int bi = 0x7fffffff;
                for (int i = lane; i < GRID; i += 32) {
                    float v  = __ldcg(&g_pVal[i]);
                    int   ix = __ldcg(&g_pIdx[i]);
                    if (v > bv || (v == bv && ix < bi)) { bv = v; bi = ix; }
                }
                #pragma unroll
                for (int off = 16; off; off >>= 1) {
                    float ov = __shfl_down_sync(0xffffffffu, bv, off);
                    int   oi = __shfl_down_sync(0xffffffffu, bi, off);
                    if (ov > bv || (ov == bv && oi < bi)) { bv = ov; bi = oi; }
                }
                if (lane == 0) sTok = (float)bi;
            }
            __syncthreads();
            x = sTok;
        }

        // cell 0 (redundant per block): g0 = g_hh0 + wih0*x + b_ih0 + b_hh0
        {
            float gi = __ldcg(&g_hh0[tid])         + wih0[tid]         * x + bih0[tid]         + bhh0[tid];
            float gf = __ldcg(&g_hh0[tid + H])     + wih0[tid + H]     * x + bih0[tid + H]     + bhh0[tid + H];
            float gg = __ldcg(&g_hh0[tid + 2 * H]) + wih0[tid + 2 * H] * x + bih0[tid + 2 * H] + bhh0[tid + 2 * H];
            float go = __ldcg(&g_hh0[tid + 3 * H]) + wih0[tid + 3 * H] * x + bih0[tid + 3 * H] + bhh0[tid + 3 * H];
            float c  = sigm(gf) * cs0[tid] + sigm(gi) * tanhf(gg);
            cs0[tid] = c;
            hs0[tid] = sigm(go) * tanhf(c);
        }
        __syncthreads();

        // wih1 @ h0_t (+ biases) -> g_ih1   (L2-resident, ~1 row/warp)
        for (int row = gw; row < FH; row += TW) {
            float acc = dot1024<0>(wih1 + (size_t)row * H, h0v, lane);
            if (lane == 0) __stcg(&g_ih1[row], acc + bih1[row] + bhh1[row]);
        }
        gsync(base + (++phase));

        // ================= Phase A =================
        // cell 1 (redundant per block): g1 = whh1@h1_{t-1} + g_ih1
        {
            const float* hh1 = g_hh1[(t + 1) & 1];
            float gi = __ldcg(&hh1[tid])         + __ldcg(&g_ih1[tid]);
            float gf = __ldcg(&hh1[tid + H])     + __ldcg(&g_ih1[tid + H]);
            float gg = __ldcg(&hh1[tid + 2 * H]) + __ldcg(&g_ih1[tid + 2 * H]);
            float go = __ldcg(&hh1[tid + 3 * H]) + __ldcg(&g_ih1[tid + 3 * H]);
            float c  = sigm(gf) * cs1[tid] + sigm(gi) * tanhf(gg);
            cs1[tid] = c;
            hs1[tid] = sigm(go) * tanhf(c);
        }
        __syncthreads();

        // Fused distributed loop: fc rows (DRAM stream) + whh0@h0_t + whh1@h1_t (L2)
        float bv = -1.0f; int bi = 0x7fffffff;   // relu'd preds >= 0
        float* orow = out + (size_t)(t + 1) * V;
        float* hh1w = g_hh1[t & 1];
        for (int idx = gw; idx < NROWS; idx += TW) {
            if (idx < V) {
                float acc = dot1024<1>(wfc + (size_t)idx * H, h1v, lane);
                if (lane == 0) {
                    float p = fmaxf(acc + bfc[idx], 0.0f);
                    __stcs(&orow[idx], p);
                    if (p > bv || (p == bv && idx < bi)) { bv = p; bi = idx; }
                }
            } else if (idx < V + FH) {
                int r = idx - V;
                float acc = dot1024<0>(whh0 + (size_t)r * H, h0v, lane);
                if (lane == 0) __stcg(&g_hh0[r], acc);
            } else {
                int r = idx - V - FH;
                float acc = dot1024<0>(whh1 + (size_t)r * H, h1v, lane);
                if (lane == 0) __stcg(&hh1w[r], acc);
            }
        }

        // block-level argmax partial
        if (lane == 0) { sVal[warp] = bv; sIdx[warp] = bi; }
        __syncthreads();
        if (warp == 0) {
            float v  = sVal[lane];
            int   ix = sIdx[lane];
            #pragma unroll
            for (int off = 16; off; off >>= 1) {
                float ov = __shfl_down_sync(0xffffffffu, v, off);
                int   oi = __shfl_down_sync(0xffffffffu, ix, off);
                if (ov > v || (ov == v && oi < ix)) { v = ov; ix = oi; }
            }
            if (lane == 0) {
                __stcg(&g_pVal[blockIdx.x], v);
                __stcg(&g_pIdx[blockIdx.x], ix);
            }
        }
        gsync(base + (++phase));
    }
}

extern "C" void kernel_launch(void* const* d_in, const int* in_sizes, int n_in,
                              void* d_out, int out_size) {
    const int*   y    = (const int*)  d_in[0];
    const float* ctx  = (const float*)d_in[1];
    const float* wih0 = (const float*)d_in[2];
    const float* whh0 = (const float*)d_in[3];
    const float* bih0 = (const float*)d_in[4];
    const float* bhh0 = (const float*)d_in[5];
    const float* wih1 = (const float*)d_in[6];
    const float* whh1 = (const float*)d_in[7];
    const float* bih1 = (const float*)d_in[8];
    const float* bhh1 = (const float*)d_in[9];
    const float* wfc  = (const float*)d_in[10];
    const float* bfc  = (const float*)d_in[11];
    float* out = (float*)d_out;

    decoder_kernel<<<GRID, NT>>>(y, ctx, wih0, whh0, bih0, bhh0,
                                 wih1, whh1, bih1, bhh1, wfc, bfc, out);
}